// round 10
// baseline (speedup 1.0000x reference)
#include <cuda_runtime.h>
#include <cstdint>
#include <cstddef>

// ---------------------------------------------------------------------------
// GraphSAGE 2-layer, sm_103a.
//   h   = relu( scatter_mean(x, src->dst) @ Wl1^T + bl1 + x @ Wr1^T )
//   out =       scatter_mean(h, src->dst) @ Wl2^T + bl2 + h @ Wr2^T
// Round 9: unroll-8 gathers (MLP 8, split accumulator chains); scan_bsum
// folded into add_off. GEMMs unchanged from R8 (FFMA2, split smem strides).
// ---------------------------------------------------------------------------

#define MAX_N 100000
#define MAX_E 1600000
#define D_IN  128

typedef unsigned long long ull;

__device__ float g_agg[(size_t)MAX_N * 128];   // layer1 agg; layer2 reuses as z|r
__device__ float g_h[(size_t)MAX_N * 128];
__device__ int   g_bin[MAX_E];
__device__ int   g_cnt[MAX_N + 1];
__device__ int   g_off[MAX_N + 1];
__device__ int   g_cur[MAX_N + 1];
__device__ int   g_bsum[128];
__device__ int   g_is64;

__device__ __forceinline__ void ffma2(ull& d, ull a, ull b) {
    asm("fma.rn.f32x2 %0, %1, %2, %3;" : "=l"(d) : "l"(a), "l"(b), "l"(d));
}
__device__ __forceinline__ void fadd2(ull& d, ull a) {
    asm("add.rn.f32x2 %0, %1, %2;" : "=l"(d) : "l"(a), "l"(d));
}

// ---------------------------------------------------------------------------
__global__ void detect_idx_kernel(const long long* __restrict__ ei, int E, long long N) {
    __shared__ int bad;
    if (threadIdx.x == 0) bad = 0;
    __syncthreads();
    int i = threadIdx.x;
    if (i < E) {
        long long v = ei[i];
        if (v < 0 || v >= N) atomicAdd(&bad, 1);
    }
    __syncthreads();
    if (threadIdx.x == 0) g_is64 = (bad == 0) ? 1 : 0;
}

// ---------------------------------------------------------------------------
// CSR binning: count -> scan -> fill
// ---------------------------------------------------------------------------
__global__ void count_kernel(const void* __restrict__ ei, int* __restrict__ cnt, int E) {
    int i = blockIdx.x * blockDim.x + threadIdx.x;
    if (i >= E) return;
    int d = g_is64 ? (int)((const long long*)ei)[(size_t)E + i]
                   : ((const int*)ei)[(size_t)E + i];
    atomicAdd(&cnt[d], 1);
}

__global__ void scan_block_kernel(const int* __restrict__ cnt, int* __restrict__ off,
                                  int* __restrict__ bsum, int N) {
    __shared__ int sm[1024];
    int tid = threadIdx.x;
    int gi  = blockIdx.x * 1024 + tid;
    int v   = (gi < N) ? cnt[gi] : 0;
    sm[tid] = v;
    __syncthreads();
#pragma unroll
    for (int s = 1; s < 1024; s <<= 1) {
        int t = (tid >= s) ? sm[tid - s] : 0;
        __syncthreads();
        sm[tid] += t;
        __syncthreads();
    }
    if (gi < N) off[gi] = sm[tid] - v;     // exclusive within block
    if (tid == 1023) bsum[blockIdx.x] = sm[1023];
}

// add_off with integrated block-sum prefix: each CTA spans exactly one
// 1024-segment (256 | 1024), so one warp reduces bsum[0..seg) redundantly.
__global__ void add_off_kernel(int* __restrict__ off, int* __restrict__ cur,
                               const int* __restrict__ bsum, int N, int E) {
    __shared__ int spref;
    int seg = (blockIdx.x * blockDim.x) >> 10;
    if (threadIdx.x < 32) {
        int s = 0;
        for (int i = threadIdx.x; i < seg; i += 32) s += bsum[i];
#pragma unroll
        for (int o = 16; o; o >>= 1) s += __shfl_down_sync(0xffffffffu, s, o);
        if (threadIdx.x == 0) spref = s;
    }
    __syncthreads();
    int gi = blockIdx.x * blockDim.x + threadIdx.x;
    if (gi < N) {
        int v = off[gi] + spref;
        off[gi] = v;
        cur[gi] = v;
    }
    if (gi == 0) { off[N] = E; cur[N] = E; }
}

__global__ void fill_kernel(const void* __restrict__ ei, int E,
                            int* __restrict__ cur, int* __restrict__ bin) {
    int i = blockIdx.x * blockDim.x + threadIdx.x;
    if (i >= E) return;
    int s, d;
    if (g_is64) {
        const long long* p = (const long long*)ei;
        s = (int)p[i];
        d = (int)p[(size_t)E + i];
    } else {
        const int* p = (const int*)ei;
        s = p[i];
        d = p[(size_t)E + i];
    }
    int pos = atomicAdd(&cur[d], 1);
    bin[pos] = s;
}

// ---------------------------------------------------------------------------
// Gather-mean, 128-wide rows. One warp per node; lane owns 16B chunk.
// Unroll-8 main loop (MLP 8), 4 accumulators, int4 index loads.
// ---------------------------------------------------------------------------
__global__ void gather128_kernel(const ulonglong2* __restrict__ feat,  // 32 u2/row
                                 const int* __restrict__ off,
                                 const int* __restrict__ bin,
                                 float4* __restrict__ agg, int N) {
    int node = (blockIdx.x * blockDim.x + threadIdx.x) >> 5;
    int lane = threadIdx.x & 31;
    if (node >= N) return;
    int s0 = off[node], s1 = off[node + 1];
    ull a0 = 0, a1 = 0, a2 = 0, a3 = 0;
    int e = s0;
    int ea = (s0 + 3) & ~3;
    for (; e < s1 && e < ea; e++) {
        ulonglong2 v = feat[(size_t)bin[e] * 32 + lane];
        fadd2(a0, v.x); fadd2(a1, v.y);
    }
    for (; e + 8 <= s1; e += 8) {
        int4 qa = *(const int4*)(bin + e);
        int4 qb = *(const int4*)(bin + e + 4);
        ulonglong2 v0 = feat[(size_t)qa.x * 32 + lane];
        ulonglong2 v1 = feat[(size_t)qa.y * 32 + lane];
        ulonglong2 v2 = feat[(size_t)qa.z * 32 + lane];
        ulonglong2 v3 = feat[(size_t)qa.w * 32 + lane];
        ulonglong2 v4 = feat[(size_t)qb.x * 32 + lane];
        ulonglong2 v5 = feat[(size_t)qb.y * 32 + lane];
        ulonglong2 v6 = feat[(size_t)qb.z * 32 + lane];
        ulonglong2 v7 = feat[(size_t)qb.w * 32 + lane];
        fadd2(a0, v0.x); fadd2(a1, v0.y);
        fadd2(a2, v1.x); fadd2(a3, v1.y);
        fadd2(a0, v2.x); fadd2(a1, v2.y);
        fadd2(a2, v3.x); fadd2(a3, v3.y);
        fadd2(a0, v4.x); fadd2(a1, v4.y);
        fadd2(a2, v5.x); fadd2(a3, v5.y);
        fadd2(a0, v6.x); fadd2(a1, v6.y);
        fadd2(a2, v7.x); fadd2(a3, v7.y);
    }
    for (; e + 4 <= s1; e += 4) {
        int4 q = *(const int4*)(bin + e);
        ulonglong2 v0 = feat[(size_t)q.x * 32 + lane];
        ulonglong2 v1 = feat[(size_t)q.y * 32 + lane];
        ulonglong2 v2 = feat[(size_t)q.z * 32 + lane];
        ulonglong2 v3 = feat[(size_t)q.w * 32 + lane];
        fadd2(a0, v0.x); fadd2(a1, v0.y);
        fadd2(a2, v1.x); fadd2(a3, v1.y);
        fadd2(a0, v2.x); fadd2(a1, v2.y);
        fadd2(a2, v3.x); fadd2(a3, v3.y);
    }
    for (; e < s1; e++) {
        ulonglong2 v = feat[(size_t)bin[e] * 32 + lane];
        fadd2(a0, v.x); fadd2(a1, v.y);
    }
    fadd2(a0, a2); fadd2(a1, a3);
    float sc = 1.0f / (float)max(s1 - s0, 1);
    float2 p0 = *(float2*)&a0, p1 = *(float2*)&a1;
    agg[(size_t)node * 32 + lane] =
        make_float4(p0.x * sc, p0.y * sc, p1.x * sc, p1.y * sc);
}

// ---------------------------------------------------------------------------
// Gather-mean over 64-wide z rows + fused epilogue: out = mean + bias + r.
// Half-warp per node; unroll-8, 4 accumulators, int4 index loads.
// ---------------------------------------------------------------------------
__global__ void gather64_add_kernel(const ulonglong2* __restrict__ z,   // 16 u2/row
                                    const int* __restrict__ off,
                                    const int* __restrict__ bin,
                                    const float4* __restrict__ r,       // 16 f4/row
                                    const float* __restrict__ bias,
                                    float4* __restrict__ out, int N) {
    int warp = (blockIdx.x * blockDim.x + threadIdx.x) >> 5;
    int lane = threadIdx.x & 31;
    int node = warp * 2 + (lane >> 4);
    int l16  = lane & 15;
    if (node >= N) return;
    int s0 = off[node], s1 = off[node + 1];
    ull a0 = 0, a1 = 0, a2 = 0, a3 = 0;
    int e = s0;
    int ea = (s0 + 3) & ~3;
    for (; e < s1 && e < ea; e++) {
        ulonglong2 v = z[(size_t)bin[e] * 16 + l16];
        fadd2(a0, v.x); fadd2(a1, v.y);
    }
    for (; e + 8 <= s1; e += 8) {
        int4 qa = *(const int4*)(bin + e);
        int4 qb = *(const int4*)(bin + e + 4);
        ulonglong2 v0 = z[(size_t)qa.x * 16 + l16];
        ulonglong2 v1 = z[(size_t)qa.y * 16 + l16];
        ulonglong2 v2 = z[(size_t)qa.z * 16 + l16];
        ulonglong2 v3 = z[(size_t)qa.w * 16 + l16];
        ulonglong2 v4 = z[(size_t)qb.x * 16 + l16];
        ulonglong2 v5 = z[(size_t)qb.y * 16 + l16];
        ulonglong2 v6 = z[(size_t)qb.z * 16 + l16];
        ulonglong2 v7 = z[(size_t)qb.w * 16 + l16];
        fadd2(a0, v0.x); fadd2(a1, v0.y);
        fadd2(a2, v1.x); fadd2(a3, v1.y);
        fadd2(a0, v2.x); fadd2(a1, v2.y);
        fadd2(a2, v3.x); fadd2(a3, v3.y);
        fadd2(a0, v4.x); fadd2(a1, v4.y);
        fadd2(a2, v5.x); fadd2(a3, v5.y);
        fadd2(a0, v6.x); fadd2(a1, v6.y);
        fadd2(a2, v7.x); fadd2(a3, v7.y);
    }
    for (; e + 4 <= s1; e += 4) {
        int4 q = *(const int4*)(bin + e);
        ulonglong2 v0 = z[(size_t)q.x * 16 + l16];
        ulonglong2 v1 = z[(size_t)q.y * 16 + l16];
        ulonglong2 v2 = z[(size_t)q.z * 16 + l16];
        ulonglong2 v3 = z[(size_t)q.w * 16 + l16];
        fadd2(a0, v0.x); fadd2(a1, v0.y);
        fadd2(a2, v1.x); fadd2(a3, v1.y);
        fadd2(a0, v2.x); fadd2(a1, v2.y);
        fadd2(a2, v3.x); fadd2(a3, v3.y);
    }
    for (; e < s1; e++) {
        ulonglong2 v = z[(size_t)bin[e] * 16 + l16];
        fadd2(a0, v.x); fadd2(a1, v.y);
    }
    fadd2(a0, a2); fadd2(a1, a3);
    float sc = 1.0f / (float)max(s1 - s0, 1);
    float2 p0 = *(float2*)&a0, p1 = *(float2*)&a1;
    float4 rv = r[(size_t)node * 16 + l16];
    float4 bv = __ldg((const float4*)bias + l16);
    out[(size_t)node * 16 + l16] =
        make_float4(p0.x * sc + bv.x + rv.x, p0.y * sc + bv.y + rv.y,
                    p1.x * sc + bv.z + rv.z, p1.y * sc + bv.w + rv.w);
}

// ---------------------------------------------------------------------------
// Layer-1 fused dual GEMM (K=256, k-paired FFMA2):
//   h = relu([agg | x] @ [Wl1 ; Wr1]^T + bl1)
// TM=128, 512 thr, thread rows lane+32*i. W stride 130 (16B-aligned frags),
// A stride 133 (odd: 2-way staging STS, 8B frags).
// ---------------------------------------------------------------------------
__global__ void __launch_bounds__(512, 1)
sage_gemm1_kernel(const float* __restrict__ agg,
                  const float* __restrict__ xin,
                  const float* __restrict__ Wl, const float* __restrict__ Wr,
                  const float* __restrict__ bias,
                  float* __restrict__ out, int N) {
    constexpr int TM  = 128;
    constexpr int TN  = 128;
    constexpr int NT  = 512;
    constexpr int KC2 = 32;            // k-pairs per chunk
    constexpr int RSW = 130;           // W row stride (float2), even
    constexpr int RSA = 133;           // A row stride (float2), odd

    extern __shared__ float2 smem2[];
    float2* Wc = smem2;                          // [128][RSW]
    float2* At = smem2 + 128 * RSW;              // [2][KC2][RSA]

    const int tid   = threadIdx.x;
    const int lane  = tid & 31;
    const int wid   = tid >> 5;
    const int node0 = blockIdx.x * TM;

    for (int idx = tid; idx < 64 * TN; idx += NT) {
        int j  = idx >> 6;
        int k2 = idx & 63;
        Wc[k2 * RSW + j]        = *(const float2*)(Wl + j * 128 + 2 * k2);
        Wc[(64 + k2) * RSW + j] = *(const float2*)(Wr + j * 128 + 2 * k2);
    }

    ull acc[4][8];
#pragma unroll
    for (int i = 0; i < 4; i++)
#pragma unroll
        for (int j = 0; j < 8; j++) acc[i][j] = 0ULL;

    auto loadA = [&](int buf, int kc) {
        const float* src = (kc < 2) ? (agg + kc * 64) : (xin + (kc - 2) * 64);
        float2* db = At + buf * (KC2 * RSA);
#pragma unroll 4
        for (int idx = tid; idx < (KC2 * TM) / 2; idx += NT) {
            int k2p  = idx & 15;        // float4 = 2 k-pairs
            int node = idx >> 4;
            int n    = node0 + node;
            float4 v = make_float4(0.f, 0.f, 0.f, 0.f);
            if (n < N) v = *(const float4*)(src + (size_t)n * 128 + 4 * k2p);
            db[(2 * k2p) * RSA + node]     = make_float2(v.x, v.y);
            db[(2 * k2p + 1) * RSA + node] = make_float2(v.z, v.w);
        }
    };

    loadA(0, 0);
    __syncthreads();   // covers Wc too

#pragma unroll 1
    for (int kc = 0; kc < 4; kc++) {
        int b = kc & 1;
        if (kc < 3) loadA(b ^ 1, kc + 1);
        const float2* Ab = At + b * (KC2 * RSA);
        const float2* Wb = Wc + (kc * KC2) * RSW;
#pragma unroll 4
        for (int kk2 = 0; kk2 < KC2; kk2++) {
            const float2* ar = Ab + kk2 * RSA + lane;
            const float2* wr = Wb + kk2 * RSW + wid * 8;
            ull a[4], w[8];
            a[0] = *(const ull*)(ar);
            a[1] = *(const ull*)(ar + 32);
            a[2] = *(const ull*)(ar + 64);
            a[3] = *(const ull*)(ar + 96);
            ulonglong2 t;
            t = *(const ulonglong2*)(wr);     w[0] = t.x; w[1] = t.y;
            t = *(const ulonglong2*)(wr + 2); w[2] = t.x; w[3] = t.y;
            t = *(const ulonglong2*)(wr + 4); w[4] = t.x; w[5] = t.y;
            t = *(const ulonglong2*)(wr + 6); w[6] = t.x; w[7] = t.y;
#pragma unroll
            for (int i = 0; i < 4; i++)
#pragma unroll
                for (int j = 0; j < 8; j++) ffma2(acc[i][j], a[i], w[j]);
        }
        __syncthreads();
    }

    float bv[8];
#pragma unroll
    for (int j = 0; j < 8; j++) bv[j] = bias[wid * 8 + j];

#pragma unroll
    for (int i = 0; i < 4; i++) {
        int n = node0 + lane + 32 * i;
        if (n < N) {
            float r[8];
#pragma unroll
            for (int j = 0; j < 8; j++) {
                float2 p = *(float2*)&acc[i][j];
                r[j] = fmaxf(p.x + p.y + bv[j], 0.0f);
            }
            *(float4*)(out + (size_t)n * TN + wid * 8)     = make_float4(r[0], r[1], r[2], r[3]);
            *(float4*)(out + (size_t)n * TN + wid * 8 + 4) = make_float4(r[4], r[5], r[6], r[7]);
        }
    }
}

// ---------------------------------------------------------------------------
// Layer-2 dual-output GEMM (K=128):  z = h @ Wl2^T,  r = h @ Wr2^T
// Fully smem-resident, single stage, one sync.
// ---------------------------------------------------------------------------
__global__ void __launch_bounds__(512, 1)
sage_gemm2_kernel(const float* __restrict__ h,
                  const float* __restrict__ Wl, const float* __restrict__ Wr,
                  float* __restrict__ z, float* __restrict__ r, int N) {
    constexpr int TM  = 128;
    constexpr int TN  = 128;
    constexpr int NT  = 512;
    constexpr int RSW = 130;
    constexpr int RSA = 133;

    extern __shared__ float2 smem2[];
    float2* Wc = smem2;                          // [64][RSW]
    float2* Ac = smem2 + 64 * RSW;               // [64][RSA]

    const int tid   = threadIdx.x;
    const int lane  = tid & 31;
    const int wid   = tid >> 5;
    const int node0 = blockIdx.x * TM;

    for (int idx = tid; idx < 64 * TN; idx += NT) {
        int j  = idx >> 6;
        int k2 = idx & 63;
        const float* srcw = (j < 64) ? (Wl + j * 128) : (Wr + (j - 64) * 128);
        Wc[k2 * RSW + j] = *(const float2*)(srcw + 2 * k2);
    }

#pragma unroll 4
    for (int idx = tid; idx < (64 * TM) / 2; idx += NT) {
        int k2p  = idx & 31;
        int node = idx >> 5;
        int n    = node0 + node;
        float4 v = make_float4(0.f, 0.f, 0.f, 0.f);
        if (n < N) v = *(const float4*)(h + (size_t)n * 128 + 4 * k2p);
        Ac[(2 * k2p) * RSA + node]     = make_float2(v.x, v.y);
        Ac[(2 * k2p + 1) * RSA + node] = make_float2(v.z, v.w);
    }

    ull acc[4][8];
#pragma unroll
    for (int i = 0; i < 4; i++)
#pragma unroll
        for (int j = 0; j < 8; j++) acc[i][j] = 0ULL;

    __syncthreads();

#pragma unroll 4
    for (int kk2 = 0; kk2 < 64; kk2++) {
        const float2* ar = Ac + kk2 * RSA + lane;
        const float2* wr = Wc + kk2 * RSW + wid * 8;
        ull a[4], w[8];
        a[0] = *(const ull*)(ar);
        a[1] = *(const ull*)(ar + 32);
        a[2] = *(const ull*)(ar + 64);
        a[3] = *(const ull*)(ar + 96);
        ulonglong2 t;
        t = *(const ulonglong2*)(wr);     w[0] = t.x; w[1] = t.y;
        t = *(const ulonglong2*)(wr + 2); w[2] = t.x; w[3] = t.y;
        t = *(const ulonglong2*)(wr + 4); w[4] = t.x; w[5] = t.y;
        t = *(const ulonglong2*)(wr + 6); w[6] = t.x; w[7] = t.y;
#pragma unroll
        for (int i = 0; i < 4; i++)
#pragma unroll
            for (int j = 0; j < 8; j++) ffma2(acc[i][j], a[i], w[j]);
    }

    const int col  = wid * 8;                    // 0..120
    float* outp    = (col < 64) ? z : r;
    const int colo = (col < 64) ? col : col - 64;

#pragma unroll
    for (int i = 0; i < 4; i++) {
        int n = node0 + lane + 32 * i;
        if (n < N) {
            float rr[8];
#pragma unroll
            for (int j = 0; j < 8; j++) {
                float2 p = *(float2*)&acc[i][j];
                rr[j] = p.x + p.y;
            }
            *(float4*)(outp + (size_t)n * 64 + colo)     = make_float4(rr[0], rr[1], rr[2], rr[3]);
            *(float4*)(outp + (size_t)n * 64 + colo + 4) = make_float4(rr[4], rr[5], rr[6], rr[7]);
        }
    }
}

// ---------------------------------------------------------------------------

extern "C" void kernel_launch(void* const* d_in, const int* in_sizes, int n_in,
                              void* d_out, int out_size) {
    const float* x   = (const float*)d_in[0];
    const void*  ei  = d_in[1];
    const float* Wl1 = (const float*)d_in[2];
    const float* bl1 = (const float*)d_in[3];
    const float* Wr1 = (const float*)d_in[4];
    const float* Wl2 = (const float*)d_in[5];
    const float* bl2 = (const float*)d_in[6];
    const float* Wr2 = (const float*)d_in[7];
    float* out = (float*)d_out;

    int N = in_sizes[0] / D_IN;
    int E = in_sizes[1] / 2;

    float *agg, *h;
    int *bin, *cnt, *off, *cur, *bsum;
    cudaGetSymbolAddress((void**)&agg,  g_agg);
    cudaGetSymbolAddress((void**)&h,    g_h);
    cudaGetSymbolAddress((void**)&bin,  g_bin);
    cudaGetSymbolAddress((void**)&cnt,  g_cnt);
    cudaGetSymbolAddress((void**)&off,  g_off);
    cudaGetSymbolAddress((void**)&cur,  g_cur);
    cudaGetSymbolAddress((void**)&bsum, g_bsum);

    float* zbuf = agg;
    float* rbuf = agg + (size_t)N * 64;

    constexpr int SMEM1 = (128 * 130 + 2 * 32 * 133) * 8;  // 201216 B
    constexpr int SMEM2 = (64 * 130 + 64 * 133) * 8;       // 134656 B
    cudaFuncSetAttribute(sage_gemm1_kernel, cudaFuncAttributeMaxDynamicSharedMemorySize, SMEM1);
    cudaFuncSetAttribute(sage_gemm2_kernel, cudaFuncAttributeMaxDynamicSharedMemorySize, SMEM2);

    const int TB = 256;
    int nbE = (E + TB - 1) / TB;
    int nbScan = (N + 1023) / 1024;

    // --- edge normalization + CSR binning (shared by both layers) ---
    detect_idx_kernel<<<1, 256>>>((const long long*)ei, E, (long long)N);
    cudaMemsetAsync(cnt, 0, (size_t)(N + 1) * sizeof(int));
    count_kernel<<<nbE, TB>>>(ei, cnt, E);
    scan_block_kernel<<<nbScan, 1024>>>(cnt, off, bsum, N);
    add_off_kernel<<<(N + TB - 1) / TB, TB>>>(off, cur, bsum, N, E);
    fill_kernel<<<nbE, TB>>>(ei, E, cur, bin);

    // --- layer 1 ---
    gather128_kernel<<<(N * 32 + TB - 1) / TB, TB>>>(
        (const ulonglong2*)x, off, bin, (float4*)agg, N);
    sage_gemm1_kernel<<<(N + 127) / 128, 512, SMEM1>>>(agg, x, Wl1, Wr1, bl1, h, N);

    // --- layer 2: transform first, then gather (linearity of mean) ---
    sage_gemm2_kernel<<<(N + 127) / 128, 512, SMEM2>>>(h, Wl2, Wr2, zbuf, rbuf, N);
    gather64_add_kernel<<<((N + 1) / 2 * 32 + TB - 1) / TB, TB>>>(
        (const ulonglong2*)zbuf, off, bin, (const float4*)rbuf, bl2, (float4*)out, N);
}